// round 15
// baseline (speedup 1.0000x reference)
#include <cuda_runtime.h>
#include <cuda_fp16.h>
#include <math.h>
#include <stdint.h>

#define BNB  2
#define NPTS 2048
#define CCH  256
#define NH   4
#define HDIM 64
#define NL   4
#define BHN  (BNB*NH)
#define EPSBN 1e-5f

// ---------------- scratch (device globals; no allocation allowed) -------------
__device__ float    g_bufA[BNB*CCH*NPTS];
__device__ float    g_bufB[BNB*CCH*NPTS];
__device__ uint32_t g_qh[BHN*32*NPTS];        // q packed half2 along o: [bh][o2][n]
__device__ uint32_t g_kh[BHN*32*NPTS];        // k packed half2 along o: [bh][o2][m]
__device__ uint32_t g_vh[BHN*64*(NPTS/2)];    // v packed half2 along n: [bh][c][n2]
__device__ __half   g_Sh[(size_t)BHN*NPTS*NPTS];  // raw scores fp16 (67MB, L2-resident)
__device__ float    g_rs[BHN*NPTS];           // 1 / rowsum(exp(S))  (no max shift)

// fast exp on the FMA pipe
__device__ __forceinline__ float fexp(float x) {
    x = fmaxf(x, -80.f);
    float t = fmaf(x, 1.44269504f, 12582912.f);
    int   e = __float_as_int(t) << 23;
    float r = t - 12582912.f;
    float f = fmaf(x, 1.44269504f, -r);
    float p = 1.54035304e-4f;
    p = fmaf(p, f, 1.33335581e-3f);
    p = fmaf(p, f, 9.61812911e-3f);
    p = fmaf(p, f, 5.55041087e-2f);
    p = fmaf(p, f, 2.40226507e-1f);
    p = fmaf(p, f, 6.93147181e-1f);
    p = fmaf(p, f, 1.0f);
    return __int_as_float(__float_as_int(p) + e);
}

__device__ __forceinline__ uint32_t h2(float a, float b) {
    __half2 h = __floats2half2_rn(a, b);
    return *reinterpret_cast<uint32_t*>(&h);
}
__device__ __forceinline__ float2 h2f(uint32_t u) {
    return __half22float2(*reinterpret_cast<__half2*>(&u));
}

#define MMA_F16(c, a, b)                                                         \
    asm volatile("mma.sync.aligned.m16n8k16.row.col.f32.f16.f16.f32 "            \
                 "{%0,%1,%2,%3},{%4,%5,%6,%7},{%8,%9},{%0,%1,%2,%3};"            \
                 : "+f"((c)[0]), "+f"((c)[1]), "+f"((c)[2]), "+f"((c)[3])        \
                 : "r"((a)[0]), "r"((a)[1]), "r"((a)[2]), "r"((a)[3]),           \
                   "r"((b)[0]), "r"((b)[1]))

// ---------------- transposes ----------------
__global__ void k_transpose_in(const float* __restrict__ x, float* __restrict__ h) {
    __shared__ float tile[32][33];
    int b = blockIdx.z;
    int n0 = blockIdx.x * 32, c0 = blockIdx.y * 32;
    int tx = threadIdx.x, ty = threadIdx.y;
    for (int i = ty; i < 32; i += 8)
        tile[i][tx] = x[(size_t)b*NPTS*CCH + (size_t)(n0+i)*CCH + c0 + tx];
    __syncthreads();
    for (int i = ty; i < 32; i += 8)
        h[(size_t)b*CCH*NPTS + (size_t)(c0+i)*NPTS + n0 + tx] = tile[tx][i];
}

__global__ void k_transpose_out(const float* __restrict__ h, float* __restrict__ out) {
    __shared__ float tile[32][33];
    int b = blockIdx.z;
    int c0 = blockIdx.x * 32, n0 = blockIdx.y * 32;
    int tx = threadIdx.x, ty = threadIdx.y;
    for (int i = ty; i < 32; i += 8)
        tile[i][tx] = h[(size_t)b*CCH*NPTS + (size_t)(c0+i)*NPTS + n0 + tx];
    __syncthreads();
    for (int i = ty; i < 32; i += 8)
        out[(size_t)b*NPTS*CCH + (size_t)(n0+i)*CCH + c0 + tx] = tile[tx][i];
}

// ---------------- full-channel GEMM (MLP / proj), pipelined ----------------
__global__ __launch_bounds__(256)
void k_mlp(const float* __restrict__ W, const float* __restrict__ in,
           float* __restrict__ out, const float* __restrict__ bvec,
           const float* __restrict__ gvec, const float* __restrict__ bevec,
           int relu) {
    __shared__ float As[64][16];
    __shared__ float Bs[16][128];
    int b  = blockIdx.z;
    int n0 = blockIdx.x * 128, o0 = blockIdx.y * 64;
    int t  = threadIdx.x, tx = t & 15, ty = t >> 4;
    const float* inb = in + (size_t)b*CCH*NPTS;
    int aoo = t >> 2, akk = (t & 3) * 4;
    int bk0 = (t*4) >> 7,        bn0 = (t*4) & 127;
    int bk1 = (1024 + t*4) >> 7, bn1 = (1024 + t*4) & 127;
    float acc[4][8] = {};
    float4 war  = *(const float4*)&W[(size_t)(o0+aoo)*CCH + akk];
    float4 wbr0 = *(const float4*)&inb[(size_t)bk0*NPTS + n0 + bn0];
    float4 wbr1 = *(const float4*)&inb[(size_t)bk1*NPTS + n0 + bn1];
    for (int kc = 0; kc < CCH; kc += 16) {
        if (kc) __syncthreads();
        *(float4*)&As[aoo][akk] = war;
        *(float4*)&Bs[bk0][bn0] = wbr0;
        *(float4*)&Bs[bk1][bn1] = wbr1;
        if (kc + 16 < CCH) {
            war  = *(const float4*)&W[(size_t)(o0+aoo)*CCH + kc + 16 + akk];
            wbr0 = *(const float4*)&inb[(size_t)(kc+16+bk0)*NPTS + n0 + bn0];
            wbr1 = *(const float4*)&inb[(size_t)(kc+16+bk1)*NPTS + n0 + bn1];
        }
        __syncthreads();
        #pragma unroll
        for (int kk = 0; kk < 16; kk++) {
            float a[4];
            #pragma unroll
            for (int i = 0; i < 4; i++) a[i] = As[ty*4+i][kk];
            float4 b0 = *(float4*)&Bs[kk][tx*8];
            float4 b1 = *(float4*)&Bs[kk][tx*8+4];
            float bb[8] = {b0.x,b0.y,b0.z,b0.w,b1.x,b1.y,b1.z,b1.w};
            #pragma unroll
            for (int i = 0; i < 4; i++)
                #pragma unroll
                for (int j = 0; j < 8; j++)
                    acc[i][j] = fmaf(a[i], bb[j], acc[i][j]);
        }
    }
    float* outb = out + (size_t)b*CCH*NPTS;
    #pragma unroll
    for (int i = 0; i < 4; i++) {
        int o = o0 + ty*4 + i;
        float alpha = 1.f, beta = 0.f;
        if (gvec) { alpha = gvec[o] * rsqrtf(1.f + EPSBN); beta = bvec[o]*alpha + bevec[o]; }
        else if (bvec) beta = bvec[o];
        float vv[8];
        #pragma unroll
        for (int j = 0; j < 8; j++) {
            vv[j] = fmaf(acc[i][j], alpha, beta);
            if (relu) vv[j] = fmaxf(vv[j], 0.f);
        }
        float4 s0 = {vv[0],vv[1],vv[2],vv[3]}, s1 = {vv[4],vv[5],vv[6],vv[7]};
        float* p = &outb[(size_t)o*NPTS + n0 + tx*8];
        *(float4*)p = s0; *(float4*)(p+4) = s1;
    }
}

// ------- fused q/k/v head GEMMs: fp32 compute, half2-packed outputs -----------
__global__ __launch_bounds__(256)
void k_qkv(const float* __restrict__ qw, const float* __restrict__ kw,
           const float* __restrict__ vw, const float* __restrict__ vbias,
           const float* __restrict__ in, uint32_t* __restrict__ qo,
           uint32_t* __restrict__ ko, uint32_t* __restrict__ vo, int l) {
    __shared__ float As[64][64];
    __shared__ float Bs[64][128];
    int n0 = blockIdx.x * 128, bh = blockIdx.y, hh = bh & (NH-1);
    int t = threadIdx.x, tx = t & 15, ty = t >> 4;
    const float* inb = in + (size_t)bh * HDIM * NPTS;
    int vbase = (l*NH + hh) * HDIM;
    size_t wof = (size_t)(l*NH + hh)*HDIM*HDIM;
    const float* Wp[3] = {qw + wof, kw + wof, vw + wof};
    float4 wr[4];
    #pragma unroll
    for (int r = 0; r < 4; r++) wr[r] = ((const float4*)Wp[0])[t + r*256];
    #pragma unroll
    for (int r = 0; r < 8; r++) {
        int idx = r*1024 + t*4;
        int cc = idx >> 7, nn = idx & 127;
        *(float4*)&Bs[cc][nn] = *(const float4*)&inb[(size_t)cc*NPTS + n0 + nn];
    }
    for (int w = 0; w < 3; w++) {
        if (w) __syncthreads();
        #pragma unroll
        for (int r = 0; r < 4; r++)
            ((float4*)As)[t + r*256] = wr[r];
        if (w < 2) {
            #pragma unroll
            for (int r = 0; r < 4; r++) wr[r] = ((const float4*)Wp[w+1])[t + r*256];
        }
        __syncthreads();
        float acc[4][8] = {};
        #pragma unroll
        for (int cc = 0; cc < 64; cc++) {
            float a[4];
            #pragma unroll
            for (int i = 0; i < 4; i++) a[i] = As[ty*4+i][cc];
            float4 b0 = *(float4*)&Bs[cc][tx*8];
            float4 b1 = *(float4*)&Bs[cc][tx*8+4];
            float bb[8] = {b0.x,b0.y,b0.z,b0.w,b1.x,b1.y,b1.z,b1.w};
            #pragma unroll
            for (int i = 0; i < 4; i++)
                #pragma unroll
                for (int j = 0; j < 8; j++)
                    acc[i][j] = fmaf(a[i], bb[j], acc[i][j]);
        }
        if (w < 2) {
            uint32_t* outb = (w == 0 ? qo : ko) + (size_t)bh * 32 * NPTS;
            #pragma unroll
            for (int pp = 0; pp < 2; pp++) {
                int i0 = pp*2;
                uint4 u0 = {h2(acc[i0][0],acc[i0+1][0]), h2(acc[i0][1],acc[i0+1][1]),
                            h2(acc[i0][2],acc[i0+1][2]), h2(acc[i0][3],acc[i0+1][3])};
                uint4 u1 = {h2(acc[i0][4],acc[i0+1][4]), h2(acc[i0][5],acc[i0+1][5]),
                            h2(acc[i0][6],acc[i0+1][6]), h2(acc[i0][7],acc[i0+1][7])};
                uint32_t* p = &outb[(size_t)(ty*2+pp)*NPTS + n0 + tx*8];
                *(uint4*)p = u0; *(uint4*)(p+4) = u1;
            }
        } else {
            uint32_t* outb = vo + (size_t)bh * 64 * (NPTS/2);
            #pragma unroll
            for (int i = 0; i < 4; i++) {
                float bb = vbias[vbase + ty*4 + i];
                uint4 u = {h2(acc[i][0]+bb, acc[i][1]+bb), h2(acc[i][2]+bb, acc[i][3]+bb),
                           h2(acc[i][4]+bb, acc[i][5]+bb), h2(acc[i][6]+bb, acc[i][7]+bb)};
                *(uint4*)&outb[(size_t)(ty*4+i)*(NPTS/2) + ((n0 + tx*8) >> 1)] = u;
            }
        }
    }
}

// ---- scores + online rowsum (no max shift), fp16 MMA, DOUBLE-BUFFERED K ----
// block = 64 n-rows x full m sweep (chunks of 128). One barrier per chunk.
__global__ __launch_bounds__(256)
void k_scores_st(const uint32_t* __restrict__ q, const uint32_t* __restrict__ k,
                 __half* __restrict__ S, float* __restrict__ rsv) {
    __shared__ uint32_t Qh[32][72];       // [o2][n]
    __shared__ uint32_t Kh[2][32][136];   // double-buffered [o2][m]
    __shared__ float Sred[64][8];
    int n0 = blockIdx.x * 64, bh = blockIdx.y;
    const uint32_t* qb = q + (size_t)bh * 32 * NPTS;
    const uint32_t* kb = k + (size_t)bh * 32 * NPTS;
    uint32_t* Su = (uint32_t*)(S + (size_t)bh * NPTS * NPTS);
    int t = threadIdx.x, warp = t >> 5, lane = t & 31;
    int gq = lane >> 2, tg = lane & 3;
    // persistent Q tile 32o2 x 64n
    #pragma unroll
    for (int r = 0; r < 2; r++) {
        int u = r*256 + t;
        int rr = u >> 4, n4 = (u & 15) * 4;
        *(uint4*)&Qh[rr][n4] = *(const uint4*)&qb[(size_t)rr*NPTS + n0 + n4];
    }
    float stS[4][2];
    #pragma unroll
    for (int i = 0; i < 4; i++)
        #pragma unroll
        for (int hf = 0; hf < 2; hf++) stS[i][hf] = 0.f;
    // prefetch K chunk 0
    uint4 kr[4];
    #pragma unroll
    for (int r = 0; r < 4; r++) {
        int u = r*256 + t;
        int rr = u >> 5, m4 = (u & 31) * 4;
        kr[r] = *(const uint4*)&kb[(size_t)rr*NPTS + m4];
    }
    int it = 0;
    for (int m0 = 0; m0 < NPTS; m0 += 128, it ^= 1) {
        // STS staged chunk into buf[it] (prev MMA used the other buffer;
        // buf[it]'s last reader finished before the previous iteration's sync)
        #pragma unroll
        for (int r = 0; r < 4; r++) {
            int u = r*256 + t;
            int rr = u >> 5, m4 = (u & 31) * 4;
            *(uint4*)&Kh[it][rr][m4] = kr[r];
        }
        if (m0 + 128 < NPTS) {            // issue next loads; fly during MMA
            #pragma unroll
            for (int r = 0; r < 4; r++) {
                int u = r*256 + t;
                int rr = u >> 5, m4 = (u & 31) * 4;
                kr[r] = *(const uint4*)&kb[(size_t)rr*NPTS + m0 + 128 + m4];
            }
        }
        __syncthreads();                   // single barrier per chunk
        float acc[4][2][4];
        #pragma unroll
        for (int i = 0; i < 4; i++)
            #pragma unroll
            for (int j = 0; j < 2; j++)
                #pragma unroll
                for (int c = 0; c < 4; c++) acc[i][j][c] = 0.f;
        #pragma unroll
        for (int kh = 0; kh < 32; kh += 8) {
            uint32_t a[4][4], b[2][2];
            #pragma unroll
            for (int ti = 0; ti < 4; ti++) {
                int nb = ti*16 + gq;
                a[ti][0] = Qh[kh+tg][nb];
                a[ti][1] = Qh[kh+tg][nb+8];
                a[ti][2] = Qh[kh+4+tg][nb];
                a[ti][3] = Qh[kh+4+tg][nb+8];
            }
            #pragma unroll
            for (int tj = 0; tj < 2; tj++) {
                int mb = warp*16 + tj*8 + gq;
                b[tj][0] = Kh[it][kh+tg][mb];
                b[tj][1] = Kh[it][kh+4+tg][mb];
            }
            #pragma unroll
            for (int ti = 0; ti < 4; ti++)
                #pragma unroll
                for (int tj = 0; tj < 2; tj++)
                    MMA_F16(acc[ti][tj], a[ti], b[tj]);
        }
        // quantize + store + rowsum on quantized values (regs/gmem only)
        #pragma unroll
        for (int ti = 0; ti < 4; ti++) {
            uint32_t us[2][2];
            #pragma unroll
            for (int tj = 0; tj < 2; tj++) {
                int n = n0 + ti*16 + gq;
                int m = m0 + warp*16 + tj*8 + 2*tg;
                uint32_t ulo = h2(acc[ti][tj][0], acc[ti][tj][1]);
                uint32_t uhi = h2(acc[ti][tj][2], acc[ti][tj][3]);
                Su[n*(NPTS/2) + (m >> 1)]     = ulo;
                Su[(n+8)*(NPTS/2) + (m >> 1)] = uhi;
                us[tj][0] = ulo; us[tj][1] = uhi;
            }
            #pragma unroll
            for (int hf = 0; hf < 2; hf++) {
                float2 a0 = h2f(us[0][hf]), a1 = h2f(us[1][hf]);
                stS[ti][hf] += fexp(a0.x) + fexp(a0.y) + fexp(a1.x) + fexp(a1.y);
            }
        }
    }
    // plain-sum butterfly over tg lanes, then across 8 warps
    #pragma unroll
    for (int ti = 0; ti < 4; ti++) {
        #pragma unroll
        for (int hf = 0; hf < 2; hf++) {
            float Sm = stS[ti][hf];
            Sm += __shfl_xor_sync(0xffffffffu, Sm, 1);
            Sm += __shfl_xor_sync(0xffffffffu, Sm, 2);
            if (tg == 0) {
                int row = ti*16 + gq + 8*hf;
                Sred[row][warp] = Sm;
            }
        }
    }
    __syncthreads();
    if (t < 64) {
        float Sm = 0.f;
        #pragma unroll
        for (int w = 0; w < 8; w++) Sm += Sred[t][w];
        rsv[bh*NPTS + n0 + t] = 1.f / Sm;
    }
}

// ------- mega dcomp (fp16 MMA, DOUBLE-BUFFERED V/P, one barrier per chunk):
//         xr = v@P + colsum + d + t-GEMM + BN + relu + residual into h ---------
__global__ __launch_bounds__(256)
void k_dcomp_mega(const uint32_t* __restrict__ v, const __half* __restrict__ S,
                  const float* __restrict__ rsv, const float* __restrict__ Wbase,
                  float* __restrict__ h, const float* __restrict__ tb,
                  const float* __restrict__ bng, const float* __restrict__ bnb,
                  int l) {
    __shared__ uint32_t pool[11264];   // 45056 B
    #define VSM(b,c,n2)  pool[(b)*2304 + (c)*36 + (n2)]          // main: 0..4608
    #define PSM(b,n2,m)  pool[4608 + (b)*2304 + (n2)*72 + (m)]   // main: 4608..9216
    #define RSF(n)       (((float*)pool)[9216 + (n)])            // main: 9216..11264
    #define WSM(o,c)     (((float*)pool)[(o)*68 + (c)])          // epi: 0..4352
    #define DSM(c,m)     (((float*)pool)[4352 + (c)*68 + (m)])   // epi: 4352..8704
    #define RED(g,m)     (((float*)pool)[8704 + (g)*64 + (m)])   // epi: 8704..9728
    #define CSI(m)       (((float*)pool)[9728 + (m)])            // epi: 9728..9792
    int m0 = blockIdx.x * 64, bh = blockIdx.y, hh = bh & (NH-1);
    int t = threadIdx.x, warp = t >> 5, lane = t & 31;
    int wc = warp >> 2, wm = warp & 3;   // 2x4: each warp 32c x 16m
    int gq = lane >> 2, tg = lane & 3;
    const uint32_t* vb = v + (size_t)bh * 64 * (NPTS/2);
    const uint32_t* Su = (const uint32_t*)(S + (size_t)bh * NPTS * NPTS);
    float* hb = h + (size_t)bh * HDIM * NPTS;
    // preload rs into smem
    #pragma unroll
    for (int r = 0; r < 2; r++) {
        int u = r*1024 + t*4;
        *(float4*)&RSF(u) = *(const float4*)&rsv[bh*NPTS + u];
    }
    float acc[2][2][4];
    #pragma unroll
    for (int i = 0; i < 2; i++)
        #pragma unroll
        for (int j = 0; j < 2; j++)
            #pragma unroll
            for (int c = 0; c < 4; c++) acc[i][j][c] = 0.f;
    float bsum[4] = {0.f, 0.f, 0.f, 0.f};
    int pr = t >> 4, pm4 = (t & 15) * 4;
    // prefetch chunk 0 (V: 2x uint4; S: 4 rows x uint2)
    uint4 vr[2];
    uint2 sr[4];
    #pragma unroll
    for (int r = 0; r < 2; r++) {
        int u = r*256 + t;
        int c = u >> 3, n2q = (u & 7) * 4;
        vr[r] = *(const uint4*)&vb[(size_t)c*(NPTS/2) + n2q];
    }
    #pragma unroll
    for (int rr = 0; rr < 4; rr++)
        sr[rr] = *(const uint2*)&Su[(size_t)(4*pr+rr)*(NPTS/2) + (m0 >> 1) + (pm4 >> 1)];
    __syncthreads();   // RSF visible before first P-build

    int it = 0;
    for (int nc = 0; nc < NPTS; nc += 64, it ^= 1) {
        // STS V chunk -> VSM[it]
        #pragma unroll
        for (int r = 0; r < 2; r++) {
            int u = r*256 + t;
            int c = u >> 3, n2q = (u & 7) * 4;
            *(uint4*)&VSM(it, c, n2q) = vr[r];
        }
        // P build from staged S regs + smem rs -> PSM[it]
        {
            float p[4][4];
            #pragma unroll
            for (int rr = 0; rr < 4; rr++) {
                float rs = RSF(nc + 4*pr + rr);
                float2 lo = h2f(sr[rr].x), hi = h2f(sr[rr].y);
                p[rr][0] = fexp(lo.x) * rs;
                p[rr][1] = fexp(lo.y) * rs;
                p[rr][2] = fexp(hi.x) * rs;
                p[rr][3] = fexp(hi.y) * rs;
            }
            #pragma unroll
            for (int j = 0; j < 4; j++)
                bsum[j] += p[0][j] + p[1][j] + p[2][j] + p[3][j];
            uint4 w0 = {h2(p[0][0],p[1][0]), h2(p[0][1],p[1][1]),
                        h2(p[0][2],p[1][2]), h2(p[0][3],p[1][3])};
            uint4 w1 = {h2(p[2][0],p[3][0]), h2(p[2][1],p[3][1]),
                        h2(p[2][2],p[3][2]), h2(p[2][3],p[3][3])};
            *(uint4*)&PSM(it, 2*pr,   pm4) = w0;
            *(uint4*)&PSM(it, 2*pr+1, pm4) = w1;
        }
        // issue next chunk's loads; fly during MMA
        if (nc + 64 < NPTS) {
            #pragma unroll
            for (int r = 0; r < 2; r++) {
                int u = r*256 + t;
                int c = u >> 3, n2q = (u & 7) * 4;
                vr[r] = *(const uint4*)&vb[(size_t)c*(NPTS/2) + ((nc+64) >> 1) + n2q];
            }
            #pragma unroll
            for (int rr = 0; rr < 4; rr++)
                sr[rr] = *(const uint2*)&Su[(size_t)(nc+64 + 4*pr+rr)*(NPTS/2)
                                            + (m0 >> 1) + (pm4 >> 1)];
        }
        __syncthreads();                   // single barrier per chunk
        // MMA: xr += V(64c x 64n) @ P(64n x 64m), 4 k16 steps from buf[it]
        #pragma unroll
        for (int nh = 0; nh < 32; nh += 8) {
            uint32_t a[2][4], b[2][2];
            #pragma unroll
            for (int ti = 0; ti < 2; ti++) {
                int cb = wc*32 + ti*16 + gq;
                a[ti][0] = VSM(it, cb,   nh+tg);
                a[ti][1] = VSM(it, cb+8, nh+tg);
                a[ti][2] = VSM(it, cb,   nh+4+tg);
                a[ti][3] = VSM(it, cb+8, nh+4+tg);
            }
            #pragma unroll
            for (int tj = 0; tj < 2; tj++) {
                int mb = wm*16 + tj*8 + gq;
                b[tj][0] = PSM(it, nh+tg,   mb);
                b[tj][1] = PSM(it, nh+4+tg, mb);
            }
            #pragma unroll
            for (int ti = 0; ti < 2; ti++)
                #pragma unroll
                for (int tj = 0; tj < 2; tj++)
                    MMA_F16(acc[ti][tj], a[ti], b[tj]);
        }
    }
    __syncthreads();   // main-loop smem free -> epilogue reuse
    #pragma unroll
    for (int j = 0; j < 4; j++) RED(pr, pm4 + j) = bsum[j];
    {
        const float* W = Wbase + (size_t)(l*NH + hh)*HDIM*HDIM;
        #pragma unroll
        for (int r = 0; r < 4; r++) {
            int u = r*1024 + t*4;
            int o = u >> 6, c4 = u & 63;
            *(float4*)&WSM(o, c4) = *(const float4*)&W[o*HDIM + c4];
        }
    }
    __syncthreads();
    if (t < 64) {
        float s = 0.f;
        #pragma unroll
        for (int g = 0; g < 16; g++) s += RED(g, t);
        CSI(t) = 1.f / (1e-9f + s);
    }
    __syncthreads();
    // d = h - xr * csinv  -> DSM
    #pragma unroll
    for (int ti = 0; ti < 2; ti++) {
        #pragma unroll
        for (int tj = 0; tj < 2; tj++) {
            int c = wc*32 + ti*16 + gq;
            int ml = wm*16 + tj*8 + 2*tg;
            float ci0 = CSI(ml), ci1 = CSI(ml+1);
            float2 h0 = *(const float2*)&hb[(size_t)c*NPTS + m0 + ml];
            float2 h1 = *(const float2*)&hb[(size_t)(c+8)*NPTS + m0 + ml];
            DSM(c,   ml)   = h0.x - acc[ti][tj][0]*ci0;
            DSM(c,   ml+1) = h0.y - acc[ti][tj][1]*ci1;
            DSM(c+8, ml)   = h1.x - acc[ti][tj][2]*ci0;
            DSM(c+8, ml+1) = h1.y - acc[ti][tj][3]*ci1;
        }
    }
    __syncthreads();
    // t-GEMM 64x64x64 + BN + relu + residual into h
    {
        int tx = t & 15, ty = t >> 4;
        float a2[4][4] = {};
        #pragma unroll
        for (int cc = 0; cc < 64; cc++) {
            float a[4];
            #pragma unroll
            for (int i = 0; i < 4; i++) a[i] = WSM(ty*4+i, cc);
            float4 bv = *(float4*)&DSM(cc, tx*4);
            float bb[4] = {bv.x, bv.y, bv.z, bv.w};
            #pragma unroll
            for (int i = 0; i < 4; i++)
                #pragma unroll
                for (int j = 0; j < 4; j++)
                    a2[i][j] = fmaf(a[i], bb[j], a2[i][j]);
        }
        int vbase = (l*NH + hh) * HDIM;
        #pragma unroll
        for (int i = 0; i < 4; i++) {
            int o = ty*4 + i;
            float alpha = bng[vbase+o] * rsqrtf(1.f + EPSBN);
            float beta  = tb[vbase+o]*alpha + bnb[vbase+o];
            float* p = &hb[(size_t)o*NPTS + m0 + tx*4];
            float4 hv = *(float4*)p;
            hv.x += fmaxf(fmaf(a2[i][0], alpha, beta), 0.f);
            hv.y += fmaxf(fmaf(a2[i][1], alpha, beta), 0.f);
            hv.z += fmaxf(fmaf(a2[i][2], alpha, beta), 0.f);
            hv.w += fmaxf(fmaf(a2[i][3], alpha, beta), 0.f);
            *(float4*)p = hv;
        }
    }
    #undef VSM
    #undef PSM
    #undef RSF
    #undef WSM
    #undef DSM
    #undef RED
    #undef CSI
}

// ---------------- host orchestration -------------------------------------------------
extern "C" void kernel_launch(void* const* d_in, const int* in_sizes, int n_in,
                              void* d_out, int out_size) {
    const float* x      = (const float*)d_in[0];
    const float* in_w1  = (const float*)d_in[1];
    const float* in_b1  = (const float*)d_in[2];
    const float* in_g1  = (const float*)d_in[3];
    const float* in_be1 = (const float*)d_in[4];
    const float* in_w2  = (const float*)d_in[5];
    const float* in_b2  = (const float*)d_in[6];
    const float* in_g2  = (const float*)d_in[7];
    const float* in_be2 = (const float*)d_in[8];
    const float* q_w    = (const float*)d_in[9];
    const float* k_w    = (const float*)d_in[10];
    const float* v_w    = (const float*)d_in[11];
    const float* v_b    = (const float*)d_in[12];
    const float* t_w    = (const float*)d_in[13];
    const float* t_b    = (const float*)d_in[14];
    const float* bn_g   = (const float*)d_in[15];
    const float* bn_b   = (const float*)d_in[16];
    const float* proj_w = (const float*)d_in[17];
    const float* proj_b = (const float*)d_in[18];

    float *hA, *hB, *rsv;
    uint32_t *qh, *kh, *vh;
    __half *Sh;
    cudaGetSymbolAddress((void**)&hA,  g_bufA);
    cudaGetSymbolAddress((void**)&hB,  g_bufB);
    cudaGetSymbolAddress((void**)&qh,  g_qh);
    cudaGetSymbolAddress((void**)&kh,  g_kh);
    cudaGetSymbolAddress((void**)&vh,  g_vh);
    cudaGetSymbolAddress((void**)&Sh,  g_Sh);
    cudaGetSymbolAddress((void**)&rsv, g_rs);

    dim3 ttb(32, 8);
    k_transpose_in<<<dim3(NPTS/32, CCH/32, BNB), ttb>>>(x, hA);

    k_mlp<<<dim3(NPTS/128, CCH/64, BNB), 256>>>(in_w1, hA, hB, in_b1, in_g1, in_be1, 1);
    k_mlp<<<dim3(NPTS/128, CCH/64, BNB), 256>>>(in_w2, hB, hA, in_b2, in_g2, in_be2, 1);

    float* h = hA;
    float* o = hB;
    for (int l = 0; l < NL; l++) {
        k_qkv<<<dim3(NPTS/128, BHN), 256>>>(q_w, k_w, v_w, v_b, h, qh, kh, vh, l);
        k_scores_st<<<dim3(NPTS/64, BHN), 256>>>(qh, kh, Sh, rsv);
        k_dcomp_mega<<<dim3(NPTS/64, BHN), 256>>>(vh, Sh, rsv, t_w, h,
                                                  t_b, bn_g, bn_b, l);
        k_mlp<<<dim3(NPTS/128, CCH/64, BNB), 256>>>(proj_w + (size_t)l*CCH*CCH, h, o,
                                                    proj_b + (size_t)l*CCH,
                                                    nullptr, nullptr, 0);
        float* tmp = h; h = o; o = tmp;
    }

    k_transpose_out<<<dim3(CCH/32, NPTS/32, BNB), ttb>>>(h, (float*)d_out);
}

// round 16
// speedup vs baseline: 1.0879x; 1.0879x over previous
#include <cuda_runtime.h>
#include <cuda_fp16.h>
#include <math.h>
#include <stdint.h>

#define BNB  2
#define NPTS 2048
#define CCH  256
#define NH   4
#define HDIM 64
#define NL   4
#define BHN  (BNB*NH)
#define EPSBN 1e-5f

// ---------------- scratch (device globals; no allocation allowed) -------------
__device__ float    g_bufA[BNB*CCH*NPTS];
__device__ float    g_bufB[BNB*CCH*NPTS];
__device__ uint32_t g_qh[BHN*32*NPTS];        // q packed half2 along o: [bh][o2][n]
__device__ uint32_t g_kh[BHN*32*NPTS];        // k packed half2 along o: [bh][o2][m]
__device__ uint32_t g_vh[BHN*64*(NPTS/2)];    // v packed half2 along n: [bh][c][n2]
__device__ __half   g_Sh[(size_t)BHN*NPTS*NPTS];  // raw scores fp16 (67MB, L2-resident)
__device__ float    g_rs[BHN*NPTS];           // 1 / rowsum(exp(S))  (no max shift)

// fast exp on the FMA pipe
__device__ __forceinline__ float fexp(float x) {
    x = fmaxf(x, -80.f);
    float t = fmaf(x, 1.44269504f, 12582912.f);
    int   e = __float_as_int(t) << 23;
    float r = t - 12582912.f;
    float f = fmaf(x, 1.44269504f, -r);
    float p = 1.54035304e-4f;
    p = fmaf(p, f, 1.33335581e-3f);
    p = fmaf(p, f, 9.61812911e-3f);
    p = fmaf(p, f, 5.55041087e-2f);
    p = fmaf(p, f, 2.40226507e-1f);
    p = fmaf(p, f, 6.93147181e-1f);
    p = fmaf(p, f, 1.0f);
    return __int_as_float(__float_as_int(p) + e);
}

__device__ __forceinline__ uint32_t h2(float a, float b) {
    __half2 h = __floats2half2_rn(a, b);
    return *reinterpret_cast<uint32_t*>(&h);
}
__device__ __forceinline__ float2 h2f(uint32_t u) {
    return __half22float2(*reinterpret_cast<__half2*>(&u));
}

#define MMA_F16(c, a, b)                                                         \
    asm volatile("mma.sync.aligned.m16n8k16.row.col.f32.f16.f16.f32 "            \
                 "{%0,%1,%2,%3},{%4,%5,%6,%7},{%8,%9},{%0,%1,%2,%3};"            \
                 : "+f"((c)[0]), "+f"((c)[1]), "+f"((c)[2]), "+f"((c)[3])        \
                 : "r"((a)[0]), "r"((a)[1]), "r"((a)[2]), "r"((a)[3]),           \
                   "r"((b)[0]), "r"((b)[1]))

// ---------------- transposes ----------------
__global__ void k_transpose_in(const float* __restrict__ x, float* __restrict__ h) {
    __shared__ float tile[32][33];
    int b = blockIdx.z;
    int n0 = blockIdx.x * 32, c0 = blockIdx.y * 32;
    int tx = threadIdx.x, ty = threadIdx.y;
    for (int i = ty; i < 32; i += 8)
        tile[i][tx] = x[(size_t)b*NPTS*CCH + (size_t)(n0+i)*CCH + c0 + tx];
    __syncthreads();
    for (int i = ty; i < 32; i += 8)
        h[(size_t)b*CCH*NPTS + (size_t)(c0+i)*NPTS + n0 + tx] = tile[tx][i];
}

__global__ void k_transpose_out(const float* __restrict__ h, float* __restrict__ out) {
    __shared__ float tile[32][33];
    int b = blockIdx.z;
    int c0 = blockIdx.x * 32, n0 = blockIdx.y * 32;
    int tx = threadIdx.x, ty = threadIdx.y;
    for (int i = ty; i < 32; i += 8)
        tile[i][tx] = h[(size_t)b*CCH*NPTS + (size_t)(c0+i)*NPTS + n0 + tx];
    __syncthreads();
    for (int i = ty; i < 32; i += 8)
        out[(size_t)b*NPTS*CCH + (size_t)(n0+i)*CCH + c0 + tx] = tile[tx][i];
}

// ---------------- full-channel GEMM (MLP / proj), pipelined ------------------
// fuse != 0: o-tile == one head's channels; epilogue computes q/k/v for layer
// `l` from the h tile held in smem (no gmem round-trip, no separate launch).
__global__ __launch_bounds__(256)
void k_mlp(const float* __restrict__ W, const float* __restrict__ in,
           float* __restrict__ out, const float* __restrict__ bvec,
           const float* __restrict__ gvec, const float* __restrict__ bevec,
           int relu,
           const float* __restrict__ qw, const float* __restrict__ kw,
           const float* __restrict__ vw, const float* __restrict__ vbias,
           uint32_t* __restrict__ qo, uint32_t* __restrict__ ko,
           uint32_t* __restrict__ vo, int l, int fuse) {
    __shared__ float As[64][16];
    __shared__ float Bs[16][128];
    __shared__ float HSM[64][132];     // fused-epilogue h tile (stride 132)
    int b  = blockIdx.z;
    int n0 = blockIdx.x * 128, o0 = blockIdx.y * 64;
    int t  = threadIdx.x, tx = t & 15, ty = t >> 4;
    const float* inb = in + (size_t)b*CCH*NPTS;
    int aoo = t >> 2, akk = (t & 3) * 4;
    int bk0 = (t*4) >> 7,        bn0 = (t*4) & 127;
    int bk1 = (1024 + t*4) >> 7, bn1 = (1024 + t*4) & 127;
    float acc[4][8] = {};
    float4 war  = *(const float4*)&W[(size_t)(o0+aoo)*CCH + akk];
    float4 wbr0 = *(const float4*)&inb[(size_t)bk0*NPTS + n0 + bn0];
    float4 wbr1 = *(const float4*)&inb[(size_t)bk1*NPTS + n0 + bn1];
    for (int kc = 0; kc < CCH; kc += 16) {
        if (kc) __syncthreads();
        *(float4*)&As[aoo][akk] = war;
        *(float4*)&Bs[bk0][bn0] = wbr0;
        *(float4*)&Bs[bk1][bn1] = wbr1;
        if (kc + 16 < CCH) {
            war  = *(const float4*)&W[(size_t)(o0+aoo)*CCH + kc + 16 + akk];
            wbr0 = *(const float4*)&inb[(size_t)(kc+16+bk0)*NPTS + n0 + bn0];
            wbr1 = *(const float4*)&inb[(size_t)(kc+16+bk1)*NPTS + n0 + bn1];
        }
        __syncthreads();
        #pragma unroll
        for (int kk = 0; kk < 16; kk++) {
            float a[4];
            #pragma unroll
            for (int i = 0; i < 4; i++) a[i] = As[ty*4+i][kk];
            float4 b0 = *(float4*)&Bs[kk][tx*8];
            float4 b1 = *(float4*)&Bs[kk][tx*8+4];
            float bb[8] = {b0.x,b0.y,b0.z,b0.w,b1.x,b1.y,b1.z,b1.w};
            #pragma unroll
            for (int i = 0; i < 4; i++)
                #pragma unroll
                for (int j = 0; j < 8; j++)
                    acc[i][j] = fmaf(a[i], bb[j], acc[i][j]);
        }
    }
    float* outb = out + (size_t)b*CCH*NPTS;
    #pragma unroll
    for (int i = 0; i < 4; i++) {
        int o = o0 + ty*4 + i;
        float alpha = 1.f, beta = 0.f;
        if (gvec) { alpha = gvec[o] * rsqrtf(1.f + EPSBN); beta = bvec[o]*alpha + bevec[o]; }
        else if (bvec) beta = bvec[o];
        float vv[8];
        #pragma unroll
        for (int j = 0; j < 8; j++) {
            vv[j] = fmaf(acc[i][j], alpha, beta);
            if (relu) vv[j] = fmaxf(vv[j], 0.f);
        }
        float4 s0 = {vv[0],vv[1],vv[2],vv[3]}, s1 = {vv[4],vv[5],vv[6],vv[7]};
        float* p = &outb[(size_t)o*NPTS + n0 + tx*8];
        *(float4*)p = s0; *(float4*)(p+4) = s1;
        if (fuse) {                     // stash h tile for fused q/k/v
            int ol = ty*4 + i;
            *(float4*)&HSM[ol][tx*8]     = s0;
            *(float4*)&HSM[ol][tx*8 + 4] = s1;
        }
    }
    if (!fuse) return;

    // ---------- fused q/k/v head GEMMs from HSM (head = blockIdx.y) ----------
    __syncthreads();    // HSM complete; main-loop As reads done
    int hh = blockIdx.y;
    int bh = b*NH + hh;
    int vbase = (l*NH + hh) * HDIM;
    size_t wof = (size_t)(l*NH + hh)*HDIM*HDIM;
    const float* Wp[3] = {qw + wof, kw + wof, vw + wof};
    float4 war2 = *(const float4*)&Wp[0][aoo*HDIM + akk];
    #pragma unroll
    for (int w = 0; w < 3; w++) {
        float acc2[4][8] = {};
        for (int kc = 0; kc < HDIM; kc += 16) {
            if (w | kc) __syncthreads();
            *(float4*)&As[aoo][akk] = war2;
            if (kc < 48)      war2 = *(const float4*)&Wp[w][aoo*HDIM + kc + 16 + akk];
            else if (w < 2)   war2 = *(const float4*)&Wp[w+1][aoo*HDIM + akk];
            __syncthreads();
            #pragma unroll
            for (int kk = 0; kk < 16; kk++) {
                float a[4];
                #pragma unroll
                for (int i = 0; i < 4; i++) a[i] = As[ty*4+i][kk];
                float4 b0 = *(float4*)&HSM[kc+kk][tx*8];
                float4 b1 = *(float4*)&HSM[kc+kk][tx*8+4];
                float bb[8] = {b0.x,b0.y,b0.z,b0.w,b1.x,b1.y,b1.z,b1.w};
                #pragma unroll
                for (int i = 0; i < 4; i++)
                    #pragma unroll
                    for (int j = 0; j < 8; j++)
                        acc2[i][j] = fmaf(a[i], bb[j], acc2[i][j]);
            }
        }
        if (w < 2) {
            uint32_t* qob = (w == 0 ? qo : ko) + (size_t)bh * 32 * NPTS;
            #pragma unroll
            for (int pp = 0; pp < 2; pp++) {
                int i0 = pp*2;
                uint4 u0 = {h2(acc2[i0][0],acc2[i0+1][0]), h2(acc2[i0][1],acc2[i0+1][1]),
                            h2(acc2[i0][2],acc2[i0+1][2]), h2(acc2[i0][3],acc2[i0+1][3])};
                uint4 u1 = {h2(acc2[i0][4],acc2[i0+1][4]), h2(acc2[i0][5],acc2[i0+1][5]),
                            h2(acc2[i0][6],acc2[i0+1][6]), h2(acc2[i0][7],acc2[i0+1][7])};
                uint32_t* p = &qob[(size_t)(ty*2+pp)*NPTS + n0 + tx*8];
                *(uint4*)p = u0; *(uint4*)(p+4) = u1;
            }
        } else {
            uint32_t* vob = vo + (size_t)bh * 64 * (NPTS/2);
            #pragma unroll
            for (int i = 0; i < 4; i++) {
                float bb = vbias[vbase + ty*4 + i];
                uint4 u = {h2(acc2[i][0]+bb, acc2[i][1]+bb), h2(acc2[i][2]+bb, acc2[i][3]+bb),
                           h2(acc2[i][4]+bb, acc2[i][5]+bb), h2(acc2[i][6]+bb, acc2[i][7]+bb)};
                *(uint4*)&vob[(size_t)(ty*4+i)*(NPTS/2) + ((n0 + tx*8) >> 1)] = u;
            }
        }
    }
}

// ---- scores + online rowsum (no max shift), fp16 MMA, prefetched K chunks ----
// block = 64 n-rows x full m sweep (chunks of 128). S stored as half.
// rowsum computed on the QUANTIZED (stored) values for consistency with dcomp.
__global__ __launch_bounds__(256)
void k_scores_st(const uint32_t* __restrict__ q, const uint32_t* __restrict__ k,
                 __half* __restrict__ S, float* __restrict__ rsv) {
    __shared__ uint32_t Qh[32][72];    // [o2][n]
    __shared__ uint32_t Kh[32][136];   // [o2][m]
    __shared__ float Sred[64][8];
    int n0 = blockIdx.x * 64, bh = blockIdx.y;
    const uint32_t* qb = q + (size_t)bh * 32 * NPTS;
    const uint32_t* kb = k + (size_t)bh * 32 * NPTS;
    uint32_t* Su = (uint32_t*)(S + (size_t)bh * NPTS * NPTS);
    int t = threadIdx.x, warp = t >> 5, lane = t & 31;
    int gq = lane >> 2, tg = lane & 3;
    // persistent Q tile 32o2 x 64n
    #pragma unroll
    for (int r = 0; r < 2; r++) {
        int u = r*256 + t;
        int rr = u >> 4, n4 = (u & 15) * 4;
        *(uint4*)&Qh[rr][n4] = *(const uint4*)&qb[(size_t)rr*NPTS + n0 + n4];
    }
    float stS[4][2];
    #pragma unroll
    for (int i = 0; i < 4; i++)
        #pragma unroll
        for (int hf = 0; hf < 2; hf++) stS[i][hf] = 0.f;
    // prefetch K chunk 0
    uint4 kr[4];
    #pragma unroll
    for (int r = 0; r < 4; r++) {
        int u = r*256 + t;
        int rr = u >> 5, m4 = (u & 31) * 4;
        kr[r] = *(const uint4*)&kb[(size_t)rr*NPTS + m4];
    }
    for (int m0 = 0; m0 < NPTS; m0 += 128) {
        __syncthreads();                  // prev MMA done reading Kh
        #pragma unroll
        for (int r = 0; r < 4; r++) {
            int u = r*256 + t;
            int rr = u >> 5, m4 = (u & 31) * 4;
            *(uint4*)&Kh[rr][m4] = kr[r];
        }
        if (m0 + 128 < NPTS) {            // issue next loads; fly during MMA
            #pragma unroll
            for (int r = 0; r < 4; r++) {
                int u = r*256 + t;
                int rr = u >> 5, m4 = (u & 31) * 4;
                kr[r] = *(const uint4*)&kb[(size_t)rr*NPTS + m0 + 128 + m4];
            }
        }
        __syncthreads();
        float acc[4][2][4];
        #pragma unroll
        for (int i = 0; i < 4; i++)
            #pragma unroll
            for (int j = 0; j < 2; j++)
                #pragma unroll
                for (int c = 0; c < 4; c++) acc[i][j][c] = 0.f;
        #pragma unroll
        for (int kh = 0; kh < 32; kh += 8) {
            uint32_t a[4][4], b[2][2];
            #pragma unroll
            for (int ti = 0; ti < 4; ti++) {
                int nb = ti*16 + gq;
                a[ti][0] = Qh[kh+tg][nb];
                a[ti][1] = Qh[kh+tg][nb+8];
                a[ti][2] = Qh[kh+4+tg][nb];
                a[ti][3] = Qh[kh+4+tg][nb+8];
            }
            #pragma unroll
            for (int tj = 0; tj < 2; tj++) {
                int mb = warp*16 + tj*8 + gq;
                b[tj][0] = Kh[kh+tg][mb];
                b[tj][1] = Kh[kh+4+tg][mb];
            }
            #pragma unroll
            for (int ti = 0; ti < 4; ti++)
                #pragma unroll
                for (int tj = 0; tj < 2; tj++)
                    MMA_F16(acc[ti][tj], a[ti], b[tj]);
        }
        // quantize + store + rowsum on quantized values (no max shift)
        #pragma unroll
        for (int ti = 0; ti < 4; ti++) {
            uint32_t us[2][2];
            #pragma unroll
            for (int tj = 0; tj < 2; tj++) {
                int n = n0 + ti*16 + gq;
                int m = m0 + warp*16 + tj*8 + 2*tg;
                uint32_t ulo = h2(acc[ti][tj][0], acc[ti][tj][1]);
                uint32_t uhi = h2(acc[ti][tj][2], acc[ti][tj][3]);
                Su[n*(NPTS/2) + (m >> 1)]     = ulo;
                Su[(n+8)*(NPTS/2) + (m >> 1)] = uhi;
                us[tj][0] = ulo; us[tj][1] = uhi;
            }
            #pragma unroll
            for (int hf = 0; hf < 2; hf++) {
                float2 a0 = h2f(us[0][hf]), a1 = h2f(us[1][hf]);
                stS[ti][hf] += fexp(a0.x) + fexp(a0.y) + fexp(a1.x) + fexp(a1.y);
            }
        }
    }
    // plain-sum butterfly over tg lanes, then across 8 warps
    #pragma unroll
    for (int ti = 0; ti < 4; ti++) {
        #pragma unroll
        for (int hf = 0; hf < 2; hf++) {
            float Sm = stS[ti][hf];
            Sm += __shfl_xor_sync(0xffffffffu, Sm, 1);
            Sm += __shfl_xor_sync(0xffffffffu, Sm, 2);
            if (tg == 0) {
                int row = ti*16 + gq + 8*hf;
                Sred[row][warp] = Sm;
            }
        }
    }
    __syncthreads();
    if (t < 64) {
        float Sm = 0.f;
        #pragma unroll
        for (int w = 0; w < 8; w++) Sm += Sred[t][w];
        rsv[bh*NPTS + n0 + t] = 1.f / Sm;
    }
}

// ------- mega dcomp (fp16 MMA, prefetched): xr = v@P + colsum + d + t-GEMM + h ---
__global__ __launch_bounds__(256)
void k_dcomp_mega(const uint32_t* __restrict__ v, const __half* __restrict__ S,
                  const float* __restrict__ rsv, const float* __restrict__ Wbase,
                  float* __restrict__ h, const float* __restrict__ tb,
                  const float* __restrict__ bng, const float* __restrict__ bnb,
                  int l) {
    __shared__ uint32_t pool[9792];   // 39168 B
    #define VSM(c,n2)  pool[(c)*36 + (n2)]             // main: 0..2304
    #define PSM(n2,m)  pool[2304 + (n2)*72 + (m)]      // main: 2304..4608
    #define RSF(n)     (((float*)pool)[4608 + (n)])            // main: 4608..6656
    #define WSM(o,c)   (((float*)pool)[(o)*68 + (c)])          // epi: 0..4352
    #define DSM(c,m)   (((float*)pool)[4352 + (c)*68 + (m)])   // epi: 4352..8704
    #define RED(g,m)   (((float*)pool)[8704 + (g)*64 + (m)])   // epi: 8704..9728
    #define CSI(m)     (((float*)pool)[9728 + (m)])            // epi: 9728..9792
    int m0 = blockIdx.x * 64, bh = blockIdx.y, hh = bh & (NH-1);
    int t = threadIdx.x, warp = t >> 5, lane = t & 31;
    int wc = warp >> 2, wm = warp & 3;   // 2x4: each warp 32c x 16m
    int gq = lane >> 2, tg = lane & 3;
    const uint32_t* vb = v + (size_t)bh * 64 * (NPTS/2);
    const uint32_t* Su = (const uint32_t*)(S + (size_t)bh * NPTS * NPTS);
    float* hb = h + (size_t)bh * HDIM * NPTS;
    // preload rs into smem (visible after first loop sync)
    #pragma unroll
    for (int r = 0; r < 2; r++) {
        int u = r*1024 + t*4;
        *(float4*)&RSF(u) = *(const float4*)&rsv[bh*NPTS + u];
    }
    float acc[2][2][4];
    #pragma unroll
    for (int i = 0; i < 2; i++)
        #pragma unroll
        for (int j = 0; j < 2; j++)
            #pragma unroll
            for (int c = 0; c < 4; c++) acc[i][j][c] = 0.f;
    float bsum[4] = {0.f, 0.f, 0.f, 0.f};
    int pr = t >> 4, pm4 = (t & 15) * 4;
    // prefetch chunk 0 (V: 2x uint4; S: 4 rows x uint2)
    uint4 vr[2];
    uint2 sr[4];
    #pragma unroll
    for (int r = 0; r < 2; r++) {
        int u = r*256 + t;
        int c = u >> 3, n2q = (u & 7) * 4;
        vr[r] = *(const uint4*)&vb[(size_t)c*(NPTS/2) + n2q];
    }
    #pragma unroll
    for (int rr = 0; rr < 4; rr++)
        sr[rr] = *(const uint2*)&Su[(size_t)(4*pr+rr)*(NPTS/2) + (m0 >> 1) + (pm4 >> 1)];

    for (int nc = 0; nc < NPTS; nc += 64) {
        __syncthreads();    // prev MMA done; first iter: RSF/prefetch visible
        // STS V
        #pragma unroll
        for (int r = 0; r < 2; r++) {
            int u = r*256 + t;
            int c = u >> 3, n2q = (u & 7) * 4;
            *(uint4*)&VSM(c, n2q) = vr[r];
        }
        // P build from staged S regs + smem rs (no max shift)
        {
            float p[4][4];
            #pragma unroll
            for (int rr = 0; rr < 4; rr++) {
                float rs = RSF(nc + 4*pr + rr);
                float2 lo = h2f(sr[rr].x), hi = h2f(sr[rr].y);
                p[rr][0] = fexp(lo.x) * rs;
                p[rr][1] = fexp(lo.y) * rs;
                p[rr][2] = fexp(hi.x) * rs;
                p[rr][3] = fexp(hi.y) * rs;
            }
            #pragma unroll
            for (int j = 0; j < 4; j++)
                bsum[j] += p[0][j] + p[1][j] + p[2][j] + p[3][j];
            uint4 w0 = {h2(p[0][0],p[1][0]), h2(p[0][1],p[1][1]),
                        h2(p[0][2],p[1][2]), h2(p[0][3],p[1][3])};
            uint4 w1 = {h2(p[2][0],p[3][0]), h2(p[2][1],p[3][1]),
                        h2(p[2][2],p[3][2]), h2(p[2][3],p[3][3])};
            *(uint4*)&PSM(2*pr,   pm4) = w0;
            *(uint4*)&PSM(2*pr+1, pm4) = w1;
        }
        // issue next chunk's loads; fly during MMA
        if (nc + 64 < NPTS) {
            #pragma unroll
            for (int r = 0; r < 2; r++) {
                int u = r*256 + t;
                int c = u >> 3, n2q = (u & 7) * 4;
                vr[r] = *(const uint4*)&vb[(size_t)c*(NPTS/2) + ((nc+64) >> 1) + n2q];
            }
            #pragma unroll
            for (int rr = 0; rr < 4; rr++)
                sr[rr] = *(const uint2*)&Su[(size_t)(nc+64 + 4*pr+rr)*(NPTS/2)
                                            + (m0 >> 1) + (pm4 >> 1)];
        }
        __syncthreads();
        // MMA: xr += V(64c x 64n) @ P(64n x 64m), 4 k16 steps
        #pragma unroll
        for (int nh = 0; nh < 32; nh += 8) {
            uint32_t a[2][4], b[2][2];
            #pragma unroll
            for (int ti = 0; ti < 2; ti++) {
                int cb = wc*32 + ti*16 + gq;
                a[ti][0] = VSM(cb,   nh+tg);
                a[ti][1] = VSM(cb+8, nh+tg);
                a[ti][2] = VSM(cb,   nh+4+tg);
                a[ti][3] = VSM(cb+8, nh+4+tg);
            }
            #pragma unroll
            for (int tj = 0; tj < 2; tj++) {
                int mb = wm*16 + tj*8 + gq;
                b[tj][0] = PSM(nh+tg,   mb);
                b[tj][1] = PSM(nh+4+tg, mb);
            }
            #pragma unroll
            for (int ti = 0; ti < 2; ti++)
                #pragma unroll
                for (int tj = 0; tj < 2; tj++)
                    MMA_F16(acc[ti][tj], a[ti], b[tj]);
        }
    }
    __syncthreads();   // main-loop smem free -> epilogue reuse
    #pragma unroll
    for (int j = 0; j < 4; j++) RED(pr, pm4 + j) = bsum[j];
    {
        const float* W = Wbase + (size_t)(l*NH + hh)*HDIM*HDIM;
        #pragma unroll
        for (int r = 0; r < 4; r++) {
            int u = r*1024 + t*4;
            int o = u >> 6, c4 = u & 63;
            *(float4*)&WSM(o, c4) = *(const float4*)&W[o*HDIM + c4];
        }
    }
    __syncthreads();
    if (t < 64) {
        float s = 0.f;
        #pragma unroll
        for (int g = 0; g < 16; g++) s += RED(g, t);
        CSI(t) = 1.f / (1e-9f + s);
    }
    __syncthreads();
    // d = h - xr * csinv  -> DSM
    #pragma unroll
    for (int ti = 0; ti < 2; ti++) {
        #pragma unroll
        for (int tj = 0; tj < 2; tj++) {
            int c = wc*32 + ti*16 + gq;
            int ml = wm*16 + tj*8 + 2*tg;
            float ci0 = CSI(ml), ci1 = CSI(ml+1);
            float2 h0 = *(const float2*)&hb[(size_t)c*NPTS + m0 + ml];
            float2 h1 = *(const float2*)&hb[(size_t)(c+8)*NPTS + m0 + ml];
            DSM(c,   ml)   = h0.x - acc[ti][tj][0]*ci0;
            DSM(c,   ml+1) = h0.y - acc[ti][tj][1]*ci1;
            DSM(c+8, ml)   = h1.x - acc[ti][tj][2]*ci0;
            DSM(c+8, ml+1) = h1.y - acc[ti][tj][3]*ci1;
        }
    }
    __syncthreads();
    // t-GEMM 64x64x64 + BN + relu + residual into h
    {
        int tx = t & 15, ty = t >> 4;
        float a2[4][4] = {};
        #pragma unroll
        for (int cc = 0; cc < 64; cc++) {
            float a[4];
            #pragma unroll
            for (int i = 0; i < 4; i++) a[i] = WSM(ty*4+i, cc);
            float4 bv = *(float4*)&DSM(cc, tx*4);
            float bb[4] = {bv.x, bv.y, bv.z, bv.w};
            #pragma unroll
            for (int i = 0; i < 4; i++)
                #pragma unroll
                for (int j = 0; j < 4; j++)
                    a2[i][j] = fmaf(a[i], bb[j], a2[i][j]);
        }
        int vbase = (l*NH + hh) * HDIM;
        #pragma unroll
        for (int i = 0; i < 4; i++) {
            int o = ty*4 + i;
            float alpha = bng[vbase+o] * rsqrtf(1.f + EPSBN);
            float beta  = tb[vbase+o]*alpha + bnb[vbase+o];
            float* p = &hb[(size_t)o*NPTS + m0 + tx*4];
            float4 hv = *(float4*)p;
            hv.x += fmaxf(fmaf(a2[i][0], alpha, beta), 0.f);
            hv.y += fmaxf(fmaf(a2[i][1], alpha, beta), 0.f);
            hv.z += fmaxf(fmaf(a2[i][2], alpha, beta), 0.f);
            hv.w += fmaxf(fmaf(a2[i][3], alpha, beta), 0.f);
            *(float4*)p = hv;
        }
    }
    #undef VSM
    #undef PSM
    #undef RSF
    #undef WSM
    #undef DSM
    #undef RED
    #undef CSI
}

// ---------------- host orchestration -------------------------------------------------
extern "C" void kernel_launch(void* const* d_in, const int* in_sizes, int n_in,
                              void* d_out, int out_size) {
    const float* x      = (const float*)d_in[0];
    const float* in_w1  = (const float*)d_in[1];
    const float* in_b1  = (const float*)d_in[2];
    const float* in_g1  = (const float*)d_in[3];
    const float* in_be1 = (const float*)d_in[4];
    const float* in_w2  = (const float*)d_in[5];
    const float* in_b2  = (const float*)d_in[6];
    const float* in_g2  = (const float*)d_in[7];
    const float* in_be2 = (const float*)d_in[8];
    const float* q_w    = (const float*)d_in[9];
    const float* k_w    = (const float*)d_in[10];
    const float* v_w    = (const float*)d_in[11];
    const float* v_b    = (const float*)d_in[12];
    const float* t_w    = (const float*)d_in[13];
    const float* t_b    = (const float*)d_in[14];
    const float* bn_g   = (const float*)d_in[15];
    const float* bn_b   = (const float*)d_in[16];
    const float* proj_w = (const float*)d_in[17];
    const float* proj_b = (const float*)d_in[18];

    float *hA, *hB, *rsv;
    uint32_t *qh, *kh, *vh;
    __half *Sh;
    cudaGetSymbolAddress((void**)&hA,  g_bufA);
    cudaGetSymbolAddress((void**)&hB,  g_bufB);
    cudaGetSymbolAddress((void**)&qh,  g_qh);
    cudaGetSymbolAddress((void**)&kh,  g_kh);
    cudaGetSymbolAddress((void**)&vh,  g_vh);
    cudaGetSymbolAddress((void**)&Sh,  g_Sh);
    cudaGetSymbolAddress((void**)&rsv, g_rs);

    dim3 ttb(32, 8);
    k_transpose_in<<<dim3(NPTS/32, CCH/32, BNB), ttb>>>(x, hA);

    dim3 mg(NPTS/128, CCH/64, BNB);
    k_mlp<<<mg, 256>>>(in_w1, hA, hB, in_b1, in_g1, in_be1, 1,
                       nullptr, nullptr, nullptr, nullptr,
                       nullptr, nullptr, nullptr, 0, 0);
    // mlp2 fused: also emits q/k/v for layer 0
    k_mlp<<<mg, 256>>>(in_w2, hB, hA, in_b2, in_g2, in_be2, 1,
                       q_w, k_w, v_w, v_b, qh, kh, vh, 0, 1);

    float* h = hA;
    float* o = hB;
    for (int l = 0; l < NL; l++) {
        k_scores_st<<<dim3(NPTS/64, BHN), 256>>>(qh, kh, Sh, rsv);
        k_dcomp_mega<<<dim3(NPTS/64, BHN), 256>>>(vh, Sh, rsv, t_w, h,
                                                  t_b, bn_g, bn_b, l);
        int fuse = (l < NL-1);
        k_mlp<<<mg, 256>>>(proj_w + (size_t)l*CCH*CCH, h, o,
                           proj_b + (size_t)l*CCH, nullptr, nullptr, 0,
                           q_w, k_w, v_w, v_b, qh, kh, vh, l+1, fuse);
        float* tmp = h; h = o; o = tmp;
    }

    k_transpose_out<<<dim3(CCH/32, NPTS/32, BNB), ttb>>>(h, (float*)d_out);
}

// round 17
// speedup vs baseline: 1.1106x; 1.0209x over previous
#include <cuda_runtime.h>
#include <cuda_fp16.h>
#include <math.h>
#include <stdint.h>

#define BNB  2
#define NPTS 2048
#define CCH  256
#define NH   4
#define HDIM 64
#define NL   4
#define BHN  (BNB*NH)
#define EPSBN 1e-5f

// ---------------- scratch (device globals; no allocation allowed) -------------
__device__ float    g_bufA[BNB*CCH*NPTS];
__device__ float    g_bufB[BNB*CCH*NPTS];
__device__ uint32_t g_qh[BHN*32*NPTS];        // q packed half2 along o: [bh][o2][n]
__device__ uint32_t g_kh[BHN*32*NPTS];        // k packed half2 along o: [bh][o2][m]
__device__ uint32_t g_vh[BHN*64*(NPTS/2)];    // v packed half2 along n: [bh][c][n2]
__device__ __half   g_Sh[(size_t)BHN*NPTS*NPTS];  // raw scores fp16 (67MB, L2-resident)
__device__ float    g_rs[BHN*NPTS];           // 1 / rowsum(exp(S))  (no max shift)

// fast exp on the FMA pipe
__device__ __forceinline__ float fexp(float x) {
    x = fmaxf(x, -80.f);
    float t = fmaf(x, 1.44269504f, 12582912.f);
    int   e = __float_as_int(t) << 23;
    float r = t - 12582912.f;
    float f = fmaf(x, 1.44269504f, -r);
    float p = 1.54035304e-4f;
    p = fmaf(p, f, 1.33335581e-3f);
    p = fmaf(p, f, 9.61812911e-3f);
    p = fmaf(p, f, 5.55041087e-2f);
    p = fmaf(p, f, 2.40226507e-1f);
    p = fmaf(p, f, 6.93147181e-1f);
    p = fmaf(p, f, 1.0f);
    return __int_as_float(__float_as_int(p) + e);
}

__device__ __forceinline__ uint32_t h2(float a, float b) {
    __half2 h = __floats2half2_rn(a, b);
    return *reinterpret_cast<uint32_t*>(&h);
}
__device__ __forceinline__ float2 h2f(uint32_t u) {
    return __half22float2(*reinterpret_cast<__half2*>(&u));
}

#define MMA_F16(c, a, b)                                                         \
    asm volatile("mma.sync.aligned.m16n8k16.row.col.f32.f16.f16.f32 "            \
                 "{%0,%1,%2,%3},{%4,%5,%6,%7},{%8,%9},{%0,%1,%2,%3};"            \
                 : "+f"((c)[0]), "+f"((c)[1]), "+f"((c)[2]), "+f"((c)[3])        \
                 : "r"((a)[0]), "r"((a)[1]), "r"((a)[2]), "r"((a)[3]),           \
                   "r"((b)[0]), "r"((b)[1]))

// ---------------- transposes ----------------
__global__ void k_transpose_in(const float* __restrict__ x, float* __restrict__ h) {
    __shared__ float tile[32][33];
    int b = blockIdx.z;
    int n0 = blockIdx.x * 32, c0 = blockIdx.y * 32;
    int tx = threadIdx.x, ty = threadIdx.y;
    for (int i = ty; i < 32; i += 8)
        tile[i][tx] = x[(size_t)b*NPTS*CCH + (size_t)(n0+i)*CCH + c0 + tx];
    __syncthreads();
    for (int i = ty; i < 32; i += 8)
        h[(size_t)b*CCH*NPTS + (size_t)(c0+i)*NPTS + n0 + tx] = tile[tx][i];
}

__global__ void k_transpose_out(const float* __restrict__ h, float* __restrict__ out) {
    __shared__ float tile[32][33];
    int b = blockIdx.z;
    int c0 = blockIdx.x * 32, n0 = blockIdx.y * 32;
    int tx = threadIdx.x, ty = threadIdx.y;
    for (int i = ty; i < 32; i += 8)
        tile[i][tx] = h[(size_t)b*CCH*NPTS + (size_t)(c0+i)*NPTS + n0 + tx];
    __syncthreads();
    for (int i = ty; i < 32; i += 8)
        out[(size_t)b*NPTS*CCH + (size_t)(n0+i)*CCH + c0 + tx] = tile[tx][i];
}

// ---------------- full-channel GEMM (MLP / proj), pipelined ----------------
__global__ __launch_bounds__(256)
void k_mlp(const float* __restrict__ W, const float* __restrict__ in,
           float* __restrict__ out, const float* __restrict__ bvec,
           const float* __restrict__ gvec, const float* __restrict__ bevec,
           int relu) {
    __shared__ float As[64][16];
    __shared__ float Bs[16][128];
    int b  = blockIdx.z;
    int n0 = blockIdx.x * 128, o0 = blockIdx.y * 64;
    int t  = threadIdx.x, tx = t & 15, ty = t >> 4;
    const float* inb = in + (size_t)b*CCH*NPTS;
    int aoo = t >> 2, akk = (t & 3) * 4;
    int bk0 = (t*4) >> 7,        bn0 = (t*4) & 127;
    int bk1 = (1024 + t*4) >> 7, bn1 = (1024 + t*4) & 127;
    float acc[4][8] = {};
    float4 war  = *(const float4*)&W[(size_t)(o0+aoo)*CCH + akk];
    float4 wbr0 = *(const float4*)&inb[(size_t)bk0*NPTS + n0 + bn0];
    float4 wbr1 = *(const float4*)&inb[(size_t)bk1*NPTS + n0 + bn1];
    for (int kc = 0; kc < CCH; kc += 16) {
        if (kc) __syncthreads();
        *(float4*)&As[aoo][akk] = war;
        *(float4*)&Bs[bk0][bn0] = wbr0;
        *(float4*)&Bs[bk1][bn1] = wbr1;
        if (kc + 16 < CCH) {
            war  = *(const float4*)&W[(size_t)(o0+aoo)*CCH + kc + 16 + akk];
            wbr0 = *(const float4*)&inb[(size_t)(kc+16+bk0)*NPTS + n0 + bn0];
            wbr1 = *(const float4*)&inb[(size_t)(kc+16+bk1)*NPTS + n0 + bn1];
        }
        __syncthreads();
        #pragma unroll
        for (int kk = 0; kk < 16; kk++) {
            float a[4];
            #pragma unroll
            for (int i = 0; i < 4; i++) a[i] = As[ty*4+i][kk];
            float4 b0 = *(float4*)&Bs[kk][tx*8];
            float4 b1 = *(float4*)&Bs[kk][tx*8+4];
            float bb[8] = {b0.x,b0.y,b0.z,b0.w,b1.x,b1.y,b1.z,b1.w};
            #pragma unroll
            for (int i = 0; i < 4; i++)
                #pragma unroll
                for (int j = 0; j < 8; j++)
                    acc[i][j] = fmaf(a[i], bb[j], acc[i][j]);
        }
    }
    float* outb = out + (size_t)b*CCH*NPTS;
    #pragma unroll
    for (int i = 0; i < 4; i++) {
        int o = o0 + ty*4 + i;
        float alpha = 1.f, beta = 0.f;
        if (gvec) { alpha = gvec[o] * rsqrtf(1.f + EPSBN); beta = bvec[o]*alpha + bevec[o]; }
        else if (bvec) beta = bvec[o];
        float vv[8];
        #pragma unroll
        for (int j = 0; j < 8; j++) {
            vv[j] = fmaf(acc[i][j], alpha, beta);
            if (relu) vv[j] = fmaxf(vv[j], 0.f);
        }
        float4 s0 = {vv[0],vv[1],vv[2],vv[3]}, s1 = {vv[4],vv[5],vv[6],vv[7]};
        float* p = &outb[(size_t)o*NPTS + n0 + tx*8];
        *(float4*)p = s0; *(float4*)(p+4) = s1;
    }
}

// ------- fused q/k/v head GEMMs: fp32 compute, half2-packed outputs -----------
__global__ __launch_bounds__(256)
void k_qkv(const float* __restrict__ qw, const float* __restrict__ kw,
           const float* __restrict__ vw, const float* __restrict__ vbias,
           const float* __restrict__ in, uint32_t* __restrict__ qo,
           uint32_t* __restrict__ ko, uint32_t* __restrict__ vo, int l) {
    __shared__ float As[64][64];
    __shared__ float Bs[64][128];
    int n0 = blockIdx.x * 128, bh = blockIdx.y, hh = bh & (NH-1);
    int t = threadIdx.x, tx = t & 15, ty = t >> 4;
    const float* inb = in + (size_t)bh * HDIM * NPTS;
    int vbase = (l*NH + hh) * HDIM;
    size_t wof = (size_t)(l*NH + hh)*HDIM*HDIM;
    const float* Wp[3] = {qw + wof, kw + wof, vw + wof};
    float4 wr[4];
    #pragma unroll
    for (int r = 0; r < 4; r++) wr[r] = ((const float4*)Wp[0])[t + r*256];
    #pragma unroll
    for (int r = 0; r < 8; r++) {
        int idx = r*1024 + t*4;
        int cc = idx >> 7, nn = idx & 127;
        *(float4*)&Bs[cc][nn] = *(const float4*)&inb[(size_t)cc*NPTS + n0 + nn];
    }
    for (int w = 0; w < 3; w++) {
        if (w) __syncthreads();
        #pragma unroll
        for (int r = 0; r < 4; r++)
            ((float4*)As)[t + r*256] = wr[r];
        if (w < 2) {
            #pragma unroll
            for (int r = 0; r < 4; r++) wr[r] = ((const float4*)Wp[w+1])[t + r*256];
        }
        __syncthreads();
        float acc[4][8] = {};
        #pragma unroll
        for (int cc = 0; cc < 64; cc++) {
            float a[4];
            #pragma unroll
            for (int i = 0; i < 4; i++) a[i] = As[ty*4+i][cc];
            float4 b0 = *(float4*)&Bs[cc][tx*8];
            float4 b1 = *(float4*)&Bs[cc][tx*8+4];
            float bb[8] = {b0.x,b0.y,b0.z,b0.w,b1.x,b1.y,b1.z,b1.w};
            #pragma unroll
            for (int i = 0; i < 4; i++)
                #pragma unroll
                for (int j = 0; j < 8; j++)
                    acc[i][j] = fmaf(a[i], bb[j], acc[i][j]);
        }
        if (w < 2) {
            uint32_t* outb = (w == 0 ? qo : ko) + (size_t)bh * 32 * NPTS;
            #pragma unroll
            for (int pp = 0; pp < 2; pp++) {
                int i0 = pp*2;
                uint4 u0 = {h2(acc[i0][0],acc[i0+1][0]), h2(acc[i0][1],acc[i0+1][1]),
                            h2(acc[i0][2],acc[i0+1][2]), h2(acc[i0][3],acc[i0+1][3])};
                uint4 u1 = {h2(acc[i0][4],acc[i0+1][4]), h2(acc[i0][5],acc[i0+1][5]),
                            h2(acc[i0][6],acc[i0+1][6]), h2(acc[i0][7],acc[i0+1][7])};
                uint32_t* p = &outb[(size_t)(ty*2+pp)*NPTS + n0 + tx*8];
                *(uint4*)p = u0; *(uint4*)(p+4) = u1;
            }
        } else {
            uint32_t* outb = vo + (size_t)bh * 64 * (NPTS/2);
            #pragma unroll
            for (int i = 0; i < 4; i++) {
                float bb = vbias[vbase + ty*4 + i];
                uint4 u = {h2(acc[i][0]+bb, acc[i][1]+bb), h2(acc[i][2]+bb, acc[i][3]+bb),
                           h2(acc[i][4]+bb, acc[i][5]+bb), h2(acc[i][6]+bb, acc[i][7]+bb)};
                *(uint4*)&outb[(size_t)(ty*4+i)*(NPTS/2) + ((n0 + tx*8) >> 1)] = u;
            }
        }
    }
}

// ---- scores + online rowsum (no max shift), fp16 MMA, Q frags HOISTED -------
// block = 64 n-rows x full m sweep (chunks of 128). S stored as half.
// Q fragments are loop-invariant: load once into registers, kill 1024 LDS/thread.
__global__ __launch_bounds__(256)
void k_scores_st(const uint32_t* __restrict__ q, const uint32_t* __restrict__ k,
                 __half* __restrict__ S, float* __restrict__ rsv) {
    __shared__ uint32_t Qh[32][72];    // [o2][n] (only used during frag hoist)
    __shared__ uint32_t Kh[32][136];   // [o2][m]
    __shared__ float Sred[64][8];
    int n0 = blockIdx.x * 64, bh = blockIdx.y;
    const uint32_t* qb = q + (size_t)bh * 32 * NPTS;
    const uint32_t* kb = k + (size_t)bh * 32 * NPTS;
    uint32_t* Su = (uint32_t*)(S + (size_t)bh * NPTS * NPTS);
    int t = threadIdx.x, warp = t >> 5, lane = t & 31;
    int gq = lane >> 2, tg = lane & 3;
    // persistent Q tile 32o2 x 64n -> smem, then hoist all fragments to regs
    #pragma unroll
    for (int r = 0; r < 2; r++) {
        int u = r*256 + t;
        int rr = u >> 4, n4 = (u & 15) * 4;
        *(uint4*)&Qh[rr][n4] = *(const uint4*)&qb[(size_t)rr*NPTS + n0 + n4];
    }
    // prefetch K chunk 0 (overlaps the Qh sync below)
    uint4 kr[4];
    #pragma unroll
    for (int r = 0; r < 4; r++) {
        int u = r*256 + t;
        int rr = u >> 5, m4 = (u & 31) * 4;
        kr[r] = *(const uint4*)&kb[(size_t)rr*NPTS + m4];
    }
    __syncthreads();
    uint32_t qa[4][4][4];              // [kstep][ti][reg] — whole-kernel A frags
    #pragma unroll
    for (int ks = 0; ks < 4; ks++) {
        int kh = ks*8;
        #pragma unroll
        for (int ti = 0; ti < 4; ti++) {
            int nb = ti*16 + gq;
            qa[ks][ti][0] = Qh[kh+tg][nb];
            qa[ks][ti][1] = Qh[kh+tg][nb+8];
            qa[ks][ti][2] = Qh[kh+4+tg][nb];
            qa[ks][ti][3] = Qh[kh+4+tg][nb+8];
        }
    }
    float stS[4][2];
    #pragma unroll
    for (int i = 0; i < 4; i++)
        #pragma unroll
        for (int hf = 0; hf < 2; hf++) stS[i][hf] = 0.f;

    for (int m0 = 0; m0 < NPTS; m0 += 128) {
        __syncthreads();                  // prev MMA done reading Kh
        #pragma unroll
        for (int r = 0; r < 4; r++) {
            int u = r*256 + t;
            int rr = u >> 5, m4 = (u & 31) * 4;
            *(uint4*)&Kh[rr][m4] = kr[r];
        }
        if (m0 + 128 < NPTS) {            // issue next loads; fly during MMA
            #pragma unroll
            for (int r = 0; r < 4; r++) {
                int u = r*256 + t;
                int rr = u >> 5, m4 = (u & 31) * 4;
                kr[r] = *(const uint4*)&kb[(size_t)rr*NPTS + m0 + 128 + m4];
            }
        }
        __syncthreads();
        float acc[4][2][4];
        #pragma unroll
        for (int i = 0; i < 4; i++)
            #pragma unroll
            for (int j = 0; j < 2; j++)
                #pragma unroll
                for (int c = 0; c < 4; c++) acc[i][j][c] = 0.f;
        #pragma unroll
        for (int ks = 0; ks < 4; ks++) {
            int kh = ks*8;
            uint32_t b[2][2];
            #pragma unroll
            for (int tj = 0; tj < 2; tj++) {
                int mb = warp*16 + tj*8 + gq;
                b[tj][0] = Kh[kh+tg][mb];
                b[tj][1] = Kh[kh+4+tg][mb];
            }
            #pragma unroll
            for (int ti = 0; ti < 4; ti++)
                #pragma unroll
                for (int tj = 0; tj < 2; tj++)
                    MMA_F16(acc[ti][tj], qa[ks][ti], b[tj]);
        }
        // quantize + store + rowsum on quantized values (no max shift)
        #pragma unroll
        for (int ti = 0; ti < 4; ti++) {
            uint32_t us[2][2];
            #pragma unroll
            for (int tj = 0; tj < 2; tj++) {
                int n = n0 + ti*16 + gq;
                int m = m0 + warp*16 + tj*8 + 2*tg;
                uint32_t ulo = h2(acc[ti][tj][0], acc[ti][tj][1]);
                uint32_t uhi = h2(acc[ti][tj][2], acc[ti][tj][3]);
                Su[n*(NPTS/2) + (m >> 1)]     = ulo;
                Su[(n+8)*(NPTS/2) + (m >> 1)] = uhi;
                us[tj][0] = ulo; us[tj][1] = uhi;
            }
            #pragma unroll
            for (int hf = 0; hf < 2; hf++) {
                float2 a0 = h2f(us[0][hf]), a1 = h2f(us[1][hf]);
                stS[ti][hf] += fexp(a0.x) + fexp(a0.y) + fexp(a1.x) + fexp(a1.y);
            }
        }
    }
    // plain-sum butterfly over tg lanes, then across 8 warps
    #pragma unroll
    for (int ti = 0; ti < 4; ti++) {
        #pragma unroll
        for (int hf = 0; hf < 2; hf++) {
            float Sm = stS[ti][hf];
            Sm += __shfl_xor_sync(0xffffffffu, Sm, 1);
            Sm += __shfl_xor_sync(0xffffffffu, Sm, 2);
            if (tg == 0) {
                int row = ti*16 + gq + 8*hf;
                Sred[row][warp] = Sm;
            }
        }
    }
    __syncthreads();
    if (t < 64) {
        float Sm = 0.f;
        #pragma unroll
        for (int w = 0; w < 8; w++) Sm += Sred[t][w];
        rsv[bh*NPTS + n0 + t] = 1.f / Sm;
    }
}

// ------- mega dcomp (fp16 MMA, prefetched): xr = v@P + colsum + d + t-GEMM + h ---
__global__ __launch_bounds__(256)
void k_dcomp_mega(const uint32_t* __restrict__ v, const __half* __restrict__ S,
                  const float* __restrict__ rsv, const float* __restrict__ Wbase,
                  float* __restrict__ h, const float* __restrict__ tb,
                  const float* __restrict__ bng, const float* __restrict__ bnb,
                  int l) {
    __shared__ uint32_t pool[9792];   // 39168 B
    #define VSM(c,n2)  pool[(c)*36 + (n2)]             // main: 0..2304
    #define PSM(n2,m)  pool[2304 + (n2)*72 + (m)]      // main: 2304..4608
    #define RSF(n)     (((float*)pool)[4608 + (n)])            // main: 4608..6656
    #define WSM(o,c)   (((float*)pool)[(o)*68 + (c)])          // epi: 0..4352
    #define DSM(c,m)   (((float*)pool)[4352 + (c)*68 + (m)])   // epi: 4352..8704
    #define RED(g,m)   (((float*)pool)[8704 + (g)*64 + (m)])   // epi: 8704..9728
    #define CSI(m)     (((float*)pool)[9728 + (m)])            // epi: 9728..9792
    int m0 = blockIdx.x * 64, bh = blockIdx.y, hh = bh & (NH-1);
    int t = threadIdx.x, warp = t >> 5, lane = t & 31;
    int wc = warp >> 2, wm = warp & 3;   // 2x4: each warp 32c x 16m
    int gq = lane >> 2, tg = lane & 3;
    const uint32_t* vb = v + (size_t)bh * 64 * (NPTS/2);
    const uint32_t* Su = (const uint32_t*)(S + (size_t)bh * NPTS * NPTS);
    float* hb = h + (size_t)bh * HDIM * NPTS;
    // preload rs into smem (visible after first loop sync)
    #pragma unroll
    for (int r = 0; r < 2; r++) {
        int u = r*1024 + t*4;
        *(float4*)&RSF(u) = *(const float4*)&rsv[bh*NPTS + u];
    }
    float acc[2][2][4];
    #pragma unroll
    for (int i = 0; i < 2; i++)
        #pragma unroll
        for (int j = 0; j < 2; j++)
            #pragma unroll
            for (int c = 0; c < 4; c++) acc[i][j][c] = 0.f;
    float bsum[4] = {0.f, 0.f, 0.f, 0.f};
    int pr = t >> 4, pm4 = (t & 15) * 4;
    // prefetch chunk 0 (V: 2x uint4; S: 4 rows x uint2)
    uint4 vr[2];
    uint2 sr[4];
    #pragma unroll
    for (int r = 0; r < 2; r++) {
        int u = r*256 + t;
        int c = u >> 3, n2q = (u & 7) * 4;
        vr[r] = *(const uint4*)&vb[(size_t)c*(NPTS/2) + n2q];
    }
    #pragma unroll
    for (int rr = 0; rr < 4; rr++)
        sr[rr] = *(const uint2*)&Su[(size_t)(4*pr+rr)*(NPTS/2) + (m0 >> 1) + (pm4 >> 1)];

    for (int nc = 0; nc < NPTS; nc += 64) {
        __syncthreads();    // prev MMA done; first iter: RSF/prefetch visible
        // STS V
        #pragma unroll
        for (int r = 0; r < 2; r++) {
            int u = r*256 + t;
            int c = u >> 3, n2q = (u & 7) * 4;
            *(uint4*)&VSM(c, n2q) = vr[r];
        }
        // P build from staged S regs + smem rs (no max shift)
        {
            float p[4][4];
            #pragma unroll
            for (int rr = 0; rr < 4; rr++) {
                float rs = RSF(nc + 4*pr + rr);
                float2 lo = h2f(sr[rr].x), hi = h2f(sr[rr].y);
                p[rr][0] = fexp(lo.x) * rs;
                p[rr][1] = fexp(lo.y) * rs;
                p[rr][2] = fexp(hi.x) * rs;
                p[rr][3] = fexp(hi.y) * rs;
            }
            #pragma unroll
            for (int j = 0; j < 4; j++)
                bsum[j] += p[0][j] + p[1][j] + p[2][j] + p[3][j];
            uint4 w0 = {h2(p[0][0],p[1][0]), h2(p[0][1],p[1][1]),
                        h2(p[0][2],p[1][2]), h2(p[0][3],p[1][3])};
            uint4 w1 = {h2(p[2][0],p[3][0]), h2(p[2][1],p[3][1]),
                        h2(p[2][2],p[3][2]), h2(p[2][3],p[3][3])};
            *(uint4*)&PSM(2*pr,   pm4) = w0;
            *(uint4*)&PSM(2*pr+1, pm4) = w1;
        }
        // issue next chunk's loads; fly during MMA
        if (nc + 64 < NPTS) {
            #pragma unroll
            for (int r = 0; r < 2; r++) {
                int u = r*256 + t;
                int c = u >> 3, n2q = (u & 7) * 4;
                vr[r] = *(const uint4*)&vb[(size_t)c*(NPTS/2) + ((nc+64) >> 1) + n2q];
            }
            #pragma unroll
            for (int rr = 0; rr < 4; rr++)
                sr[rr] = *(const uint2*)&Su[(size_t)(nc+64 + 4*pr+rr)*(NPTS/2)
                                            + (m0 >> 1) + (pm4 >> 1)];
        }
        __syncthreads();
        // MMA: xr += V(64c x 64n) @ P(64n x 64m), 4 k16 steps
        #pragma unroll
        for (int nh = 0; nh < 32; nh += 8) {
            uint32_t a[2][4], b[2][2];
            #pragma unroll
            for (int ti = 0; ti < 2; ti++) {
                int cb = wc*32 + ti*16 + gq;
                a[ti][0] = VSM(cb,   nh+tg);
                a[ti][1] = VSM(cb+8, nh+tg);
                a[ti][2] = VSM(cb,   nh+4+tg);
                a[ti][3] = VSM(cb+8, nh+4+tg);
            }
            #pragma unroll
            for (int tj = 0; tj < 2; tj++) {
                int mb = wm*16 + tj*8 + gq;
                b[tj][0] = PSM(nh+tg,   mb);
                b[tj][1] = PSM(nh+4+tg, mb);
            }
            #pragma unroll
            for (int ti = 0; ti < 2; ti++)
                #pragma unroll
                for (int tj = 0; tj < 2; tj++)
                    MMA_F16(acc[ti][tj], a[ti], b[tj]);
        }
    }
    __syncthreads();   // main-loop smem free -> epilogue reuse
    #pragma unroll
    for (int j = 0; j < 4; j++) RED(pr, pm4 + j) = bsum[j];
    {
        const float* W = Wbase + (size_t)(l*NH + hh)*HDIM*HDIM;
        #pragma unroll
        for (int r = 0; r < 4; r++) {
            int u = r*1024 + t*4;
            int o = u >> 6, c4 = u & 63;
            *(float4*)&WSM(o, c4) = *(const float4*)&W[o*HDIM + c4];
        }
    }
    __syncthreads();
    if (t < 64) {
        float s = 0.f;
        #pragma unroll
        for (int g = 0; g < 16; g++) s += RED(g, t);
        CSI(t) = 1.f / (1e-9f + s);
    }
    __syncthreads();
    // d = h - xr * csinv  -> DSM
    #pragma unroll
    for (int ti = 0; ti < 2; ti++) {
        #pragma unroll
        for (int tj = 0; tj < 2; tj++) {
            int c = wc*32 + ti*16 + gq;
            int ml = wm*16 + tj*8 + 2*tg;
            float ci0 = CSI(ml), ci1 = CSI(ml+1);
            float2 h0 = *(const float2*)&hb[(size_t)c*NPTS + m0 + ml];
            float2 h1 = *(const float2*)&hb[(size_t)(c+8)*NPTS + m0 + ml];
            DSM(c,   ml)   = h0.x - acc[ti][tj][0]*ci0;
            DSM(c,   ml+1) = h0.y - acc[ti][tj][1]*ci1;
            DSM(c+8, ml)   = h1.x - acc[ti][tj][2]*ci0;
            DSM(c+8, ml+1) = h1.y - acc[ti][tj][3]*ci1;
        }
    }
    __syncthreads();
    // t-GEMM 64x64x64 + BN + relu + residual into h
    {
        int tx = t & 15, ty = t >> 4;
        float a2[4][4] = {};
        #pragma unroll
        for (int cc = 0; cc < 64; cc++) {
            float a[4];
            #pragma unroll
            for (int i = 0; i < 4; i++) a[i] = WSM(ty*4+i, cc);
            float4 bv = *(float4*)&DSM(cc, tx*4);
            float bb[4] = {bv.x, bv.y, bv.z, bv.w};
            #pragma unroll
            for (int i = 0; i < 4; i++)
                #pragma unroll
                for (int j = 0; j < 4; j++)
                    a2[i][j] = fmaf(a[i], bb[j], a2[i][j]);
        }
        int vbase = (l*NH + hh) * HDIM;
        #pragma unroll
        for (int i = 0; i < 4; i++) {
            int o = ty*4 + i;
            float alpha = bng[vbase+o] * rsqrtf(1.f + EPSBN);
            float beta  = tb[vbase+o]*alpha + bnb[vbase+o];
            float* p = &hb[(size_t)o*NPTS + m0 + tx*4];
            float4 hv = *(float4*)p;
            hv.x += fmaxf(fmaf(a2[i][0], alpha, beta), 0.f);
            hv.y += fmaxf(fmaf(a2[i][1], alpha, beta), 0.f);
            hv.z += fmaxf(fmaf(a2[i][2], alpha, beta), 0.f);
            hv.w += fmaxf(fmaf(a2[i][3], alpha, beta), 0.f);
            *(float4*)p = hv;
        }
    }
    #undef VSM
    #undef PSM
    #undef RSF
    #undef WSM
    #undef DSM
    #undef RED
    #undef CSI
}

// ---------------- host orchestration -------------------------------------------------
extern "C" void kernel_launch(void* const* d_in, const int* in_sizes, int n_in,
                              void* d_out, int out_size) {
    const float* x      = (const float*)d_in[0];
    const float* in_w1  = (const float*)d_in[1];
    const float* in_b1  = (const float*)d_in[2];
    const float* in_g1  = (const float*)d_in[3];
    const float* in_be1 = (const float*)d_in[4];
    const float* in_w2  = (const float*)d_in[5];
    const float* in_b2  = (const float*)d_in[6];
    const float* in_g2  = (const float*)d_in[7];
    const float* in_be2 = (const float*)d_in[8];
    const float* q_w    = (const float*)d_in[9];
    const float* k_w    = (const float*)d_in[10];
    const float* v_w    = (const float*)d_in[11];
    const float* v_b    = (const float*)d_in[12];
    const float* t_w    = (const float*)d_in[13];
    const float* t_b    = (const float*)d_in[14];
    const float* bn_g   = (const float*)d_in[15];
    const float* bn_b   = (const float*)d_in[16];
    const float* proj_w = (const float*)d_in[17];
    const float* proj_b = (const float*)d_in[18];

    float *hA, *hB, *rsv;
    uint32_t *qh, *kh, *vh;
    __half *Sh;
    cudaGetSymbolAddress((void**)&hA,  g_bufA);
    cudaGetSymbolAddress((void**)&hB,  g_bufB);
    cudaGetSymbolAddress((void**)&qh,  g_qh);
    cudaGetSymbolAddress((void**)&kh,  g_kh);
    cudaGetSymbolAddress((void**)&vh,  g_vh);
    cudaGetSymbolAddress((void**)&Sh,  g_Sh);
    cudaGetSymbolAddress((void**)&rsv, g_rs);

    dim3 ttb(32, 8);
    k_transpose_in<<<dim3(NPTS/32, CCH/32, BNB), ttb>>>(x, hA);

    k_mlp<<<dim3(NPTS/128, CCH/64, BNB), 256>>>(in_w1, hA, hB, in_b1, in_g1, in_be1, 1);
    k_mlp<<<dim3(NPTS/128, CCH/64, BNB), 256>>>(in_w2, hB, hA, in_b2, in_g2, in_be2, 1);

    float* h = hA;
    float* o = hB;
    for (int l = 0; l < NL; l++) {
        k_qkv<<<dim3(NPTS/128, BHN), 256>>>(q_w, k_w, v_w, v_b, h, qh, kh, vh, l);
        k_scores_st<<<dim3(NPTS/64, BHN), 256>>>(qh, kh, Sh, rsv);
        k_dcomp_mega<<<dim3(NPTS/64, BHN), 256>>>(vh, Sh, rsv, t_w, h,
                                                  t_b, bn_g, bn_b, l);
        k_mlp<<<dim3(NPTS/128, CCH/64, BNB), 256>>>(proj_w + (size_t)l*CCH*CCH, h, o,
                                                    proj_b + (size_t)l*CCH,
                                                    nullptr, nullptr, 0);
        float* tmp = h; h = o; o = tmp;
    }

    k_transpose_out<<<dim3(CCH/32, NPTS/32, BNB), ttb>>>(h, (float*)d_out);
}